// round 1
// baseline (speedup 1.0000x reference)
#include <cuda_runtime.h>
#include <math.h>

#define NTOK 4096
#define CDIM 2048
#define FDIM 1024
#define NEXP 8
#define RPAD (2 * NTOK + NEXP * 64)   // 8704 padded permuted rows

// ---------------- device scratch (no allocations allowed) ----------------
__device__ int   g_te[NTOK * 2];     // per-token top2 expert ids
__device__ float g_tp[NTOK * 2];     // per-token top2 probs
__device__ int   g_cnt[NEXP];
__device__ int   g_fill[NEXP];
__device__ int   g_base[NEXP];       // padded row base per expert
__device__ int   g_tok[RPAD];        // permuted row -> token (-1 = padding)
__device__ float g_w[RPAD];          // permuted row -> combine weight
__device__ float g_H[(size_t)RPAD * FDIM];  // ~35.6 MB intermediate

// ---------------- init: zero out + counters, tok = -1 ----------------
__global__ void init_kernel(float4* out4) {
    int i = blockIdx.x * blockDim.x + threadIdx.x;
    if (i < (NTOK * CDIM) / 4) out4[i] = make_float4(0.f, 0.f, 0.f, 0.f);
    if (i < RPAD) g_tok[i] = -1;
    if (i < NEXP) { g_cnt[i] = 0; g_fill[i] = 0; }
}

// ---------------- router: one block per token ----------------
__global__ void router_kernel(const float* __restrict__ x,
                              const float* __restrict__ wr) {
    __shared__ float xs[CDIM];
    __shared__ float lg[NEXP];
    int t = blockIdx.x;
    const float4* xrow = (const float4*)(x + (size_t)t * CDIM);
    for (int i = threadIdx.x; i < CDIM / 4; i += blockDim.x)
        ((float4*)xs)[i] = xrow[i];
    __syncthreads();

    int warp = threadIdx.x >> 5, lane = threadIdx.x & 31;
    float s = 0.f;
    #pragma unroll 8
    for (int c = lane; c < CDIM; c += 32)
        s += xs[c] * wr[c * NEXP + warp];
    #pragma unroll
    for (int o = 16; o > 0; o >>= 1) s += __shfl_xor_sync(0xFFFFFFFFu, s, o);
    if (lane == 0) lg[warp] = s;
    __syncthreads();

    if (threadIdx.x == 0) {
        int i0 = 0; float v0 = lg[0];
        #pragma unroll
        for (int e = 1; e < NEXP; e++) if (lg[e] > v0) { v0 = lg[e]; i0 = e; }
        int i1 = -1; float v1 = -INFINITY;
        #pragma unroll
        for (int e = 0; e < NEXP; e++)
            if (e != i0 && lg[e] > v1) { v1 = lg[e]; i1 = e; }
        float e1 = __expf(v1 - v0);
        float inv = 1.f / (1.f + e1);
        g_te[t * 2 + 0] = i0;  g_tp[t * 2 + 0] = inv;
        g_te[t * 2 + 1] = i1;  g_tp[t * 2 + 1] = e1 * inv;
        atomicAdd(&g_cnt[i0], 1);
        atomicAdd(&g_cnt[i1], 1);
    }
}

// ---------------- offsets: pad counts to 64-row tiles ----------------
__global__ void offsets_kernel() {
    if (threadIdx.x == 0) {
        int b = 0;
        for (int e = 0; e < NEXP; e++) {
            g_base[e] = b;
            b += ((g_cnt[e] + 63) >> 6) << 6;
        }
    }
}

// ---------------- scatter: build permuted row lists ----------------
__global__ void scatter_kernel() {
    int t = blockIdx.x * blockDim.x + threadIdx.x;
    if (t >= NTOK) return;
    #pragma unroll
    for (int k = 0; k < 2; k++) {
        int e = g_te[t * 2 + k];
        int pos = g_base[e] + atomicAdd(&g_fill[e], 1);
        g_tok[pos] = t;
        g_w[pos] = g_tp[t * 2 + k];
    }
}

// ---------------- GEMM1: H = (silu(X@w1) * (X@w3)) * weight ----------------
// grid: (FDIM/64, 64 row-tiles, 8 experts), 256 threads, 64x64x16 tiles
__global__ __launch_bounds__(256) void gemm1_kernel(
    const float* __restrict__ x,
    const float* __restrict__ w1,
    const float* __restrict__ w3) {
    int e = blockIdx.z;
    int cnt = g_cnt[e];
    int rt = blockIdx.y;
    if (rt * 64 >= cnt) return;
    int r0 = g_base[e] + rt * 64;
    int f0 = blockIdx.x * 64;

    __shared__ float As[16][68];
    __shared__ float B1s[16][64];
    __shared__ float B2s[16][64];
    __shared__ int   s_tok[64];
    __shared__ float s_w[64];

    int t = threadIdx.x;
    if (t < 64) {
        int tok = g_tok[r0 + t];
        s_w[t]   = (tok < 0) ? 0.f : g_w[r0 + t];
        s_tok[t] = (tok < 0) ? 0 : tok;
    }
    __syncthreads();

    int tx = t & 15, ty = t >> 4;
    int am = t >> 2;          // 0..63 row to load
    int ak = (t & 3) * 4;     // k sub-offset
    int bk = t >> 4;          // 0..15
    int bf = (t & 15) * 4;

    const float* w1e = w1 + (size_t)e * CDIM * FDIM + f0;
    const float* w3e = w3 + (size_t)e * CDIM * FDIM + f0;
    int mytok = s_tok[am];

    float accg[4][4] = {{0.f}};
    float accu[4][4] = {{0.f}};

    for (int k0 = 0; k0 < CDIM; k0 += 16) {
        float4 av = *(const float4*)(x + (size_t)mytok * CDIM + k0 + ak);
        As[ak + 0][am] = av.x; As[ak + 1][am] = av.y;
        As[ak + 2][am] = av.z; As[ak + 3][am] = av.w;
        *(float4*)&B1s[bk][bf] = *(const float4*)&w1e[(size_t)(k0 + bk) * FDIM + bf];
        *(float4*)&B2s[bk][bf] = *(const float4*)&w3e[(size_t)(k0 + bk) * FDIM + bf];
        __syncthreads();
        #pragma unroll
        for (int kk = 0; kk < 16; kk++) {
            float4 a4  = *(const float4*)&As[kk][ty * 4];
            float4 b14 = *(const float4*)&B1s[kk][tx * 4];
            float4 b24 = *(const float4*)&B2s[kk][tx * 4];
            float aa[4]  = {a4.x, a4.y, a4.z, a4.w};
            float bb1[4] = {b14.x, b14.y, b14.z, b14.w};
            float bb2[4] = {b24.x, b24.y, b24.z, b24.w};
            #pragma unroll
            for (int i = 0; i < 4; i++)
                #pragma unroll
                for (int j = 0; j < 4; j++) {
                    accg[i][j] += aa[i] * bb1[j];
                    accu[i][j] += aa[i] * bb2[j];
                }
        }
        __syncthreads();
    }

    #pragma unroll
    for (int i = 0; i < 4; i++) {
        int m = ty * 4 + i;
        float w = s_w[m];
        float4 h4;
        float hv[4];
        #pragma unroll
        for (int j = 0; j < 4; j++) {
            float g = accg[i][j];
            float sig = 1.f / (1.f + __expf(-g));
            hv[j] = g * sig * accu[i][j] * w;
        }
        h4.x = hv[0]; h4.y = hv[1]; h4.z = hv[2]; h4.w = hv[3];
        *(float4*)&g_H[(size_t)(r0 + m) * FDIM + f0 + tx * 4] = h4;
    }
}

// ---------------- GEMM2: out[token] += H @ w2[e] ----------------
// grid: (CDIM/64, 64 row-tiles, 8 experts), 256 threads
__global__ __launch_bounds__(256) void gemm2_kernel(
    const float* __restrict__ w2,
    float* __restrict__ out) {
    int e = blockIdx.z;
    int cnt = g_cnt[e];
    int rt = blockIdx.y;
    if (rt * 64 >= cnt) return;
    int r0 = g_base[e] + rt * 64;
    int c0 = blockIdx.x * 64;

    __shared__ float As[16][68];
    __shared__ float Bs[16][64];
    __shared__ int s_tok[64];

    int t = threadIdx.x;
    if (t < 64) s_tok[t] = g_tok[r0 + t];
    __syncthreads();

    int tx = t & 15, ty = t >> 4;
    int am = t >> 2;
    int ak = (t & 3) * 4;
    int bk = t >> 4;
    int bc = (t & 15) * 4;

    const float* w2e = w2 + (size_t)e * FDIM * CDIM + c0;
    const float* Arow = g_H + (size_t)(r0 + am) * FDIM;

    float acc[4][4] = {{0.f}};

    for (int k0 = 0; k0 < FDIM; k0 += 16) {
        float4 av = *(const float4*)(Arow + k0 + ak);
        As[ak + 0][am] = av.x; As[ak + 1][am] = av.y;
        As[ak + 2][am] = av.z; As[ak + 3][am] = av.w;
        *(float4*)&Bs[bk][bc] = *(const float4*)&w2e[(size_t)(k0 + bk) * CDIM + bc];
        __syncthreads();
        #pragma unroll
        for (int kk = 0; kk < 16; kk++) {
            float4 a4 = *(const float4*)&As[kk][ty * 4];
            float4 b4 = *(const float4*)&Bs[kk][tx * 4];
            float aa[4] = {a4.x, a4.y, a4.z, a4.w};
            float bb[4] = {b4.x, b4.y, b4.z, b4.w};
            #pragma unroll
            for (int i = 0; i < 4; i++)
                #pragma unroll
                for (int j = 0; j < 4; j++)
                    acc[i][j] += aa[i] * bb[j];
        }
        __syncthreads();
    }

    #pragma unroll
    for (int i = 0; i < 4; i++) {
        int m = ty * 4 + i;
        int tok = s_tok[m];
        if (tok < 0) continue;
        float* orow = out + (size_t)tok * CDIM + c0 + tx * 4;
        #pragma unroll
        for (int j = 0; j < 4; j++)
            atomicAdd(&orow[j], acc[i][j]);
    }
}

// ---------------- launch ----------------
extern "C" void kernel_launch(void* const* d_in, const int* in_sizes, int n_in,
                              void* d_out, int out_size) {
    const float* x  = (const float*)d_in[0];   // [2,2048,2048] -> [4096,2048]
    const float* wr = (const float*)d_in[1];   // [2048,8]
    const float* w1 = (const float*)d_in[2];   // [8,2048,1024]
    const float* w3 = (const float*)d_in[3];   // [8,2048,1024]
    const float* w2 = (const float*)d_in[4];   // [8,1024,2048]
    float* out = (float*)d_out;

    // init: covers max(out float4 count, RPAD)
    int init_elems = (NTOK * CDIM) / 4;       // 2,097,152
    init_kernel<<<(init_elems + 255) / 256, 256>>>((float4*)out);

    router_kernel<<<NTOK, 256>>>(x, wr);
    offsets_kernel<<<1, 32>>>();
    scatter_kernel<<<(NTOK + 255) / 256, 256>>>();

    dim3 g1(FDIM / 64, 64, NEXP);   // (16, 64, 8)
    gemm1_kernel<<<g1, 256>>>(x, w1, w3);

    dim3 g2(CDIM / 64, 64, NEXP);   // (32, 64, 8)
    gemm2_kernel<<<g2, 256>>>(w2, out);
}

// round 4
// speedup vs baseline: 3.1052x; 3.1052x over previous
#include <cuda_runtime.h>
#include <math.h>
#include <stdint.h>

#if defined(__CUDA_ARCH__) && defined(__CUDA_ARCH_FEAT_SM103_ALL)
#define USE_TC 1
#else
#define USE_TC 0
#endif

#define NTOK 4096
#define CDIM 2048
#define FDIM 1024
#define NEXP 8
#define RPAD (2*NTOK + NEXP*128)   // 9216 padded permuted rows

// ---------------- device scratch ----------------
__device__ int   g_te[NTOK*2];
__device__ float g_tp[NTOK*2];
__device__ int   g_cnt[NEXP];
__device__ int   g_fill[NEXP];
__device__ int   g_base[NEXP];
__device__ int   g_tok[RPAD];
__device__ float g_w[RPAD];
__device__ float g_H[(size_t)RPAD * FDIM];
__device__ float g_w1t[(size_t)NEXP*FDIM*CDIM];   // [E][F][C] K-major tf32
__device__ float g_w3t[(size_t)NEXP*FDIM*CDIM];
__device__ float g_w2t[(size_t)NEXP*CDIM*FDIM];   // [E][C][F] K-major tf32

// ---------------- helpers ----------------
__device__ __forceinline__ uint32_t smem_u32(const void* p) {
    uint32_t a;
    asm("{ .reg .u64 t; cvta.to.shared.u64 t, %1; cvt.u32.u64 %0, t; }" : "=r"(a) : "l"(p));
    return a;
}
__device__ __forceinline__ float to_tf32(float x) {
    float r; asm("cvt.rna.tf32.f32 %0, %1;" : "=f"(r) : "f"(x)); return r;
}

#if USE_TC
__device__ __forceinline__ uint32_t elect_one() {
    uint32_t p;
    asm volatile("{ .reg .pred p; elect.sync _|p, 0xFFFFFFFF; selp.b32 %0, 1, 0, p; }" : "=r"(p));
    return p;
}
#define MBAR_INIT(a, c) asm volatile("mbarrier.init.shared.b64 [%0], %1;" :: "r"(a), "r"(c) : "memory")
__device__ __forceinline__ void mbar_wait(uint32_t addr, uint32_t parity) {
    asm volatile(
        "{\n\t.reg .pred P;\n\t"
        "W_%=:\n\t"
        "mbarrier.try_wait.parity.acquire.cta.shared::cta.b64 P, [%0], %1, 0x989680;\n\t"
        "@P bra D_%=;\n\t"
        "bra W_%=;\n\t"
        "D_%=:\n\t}"
        :: "r"(addr), "r"(parity) : "memory");
}
#define TC_ALLOC(sa, n)   asm volatile("tcgen05.alloc.cta_group::1.sync.aligned.shared::cta.b32 [%0], %1;" :: "r"(sa), "r"(n) : "memory")
#define TC_DEALLOC(t, n)  asm volatile("tcgen05.dealloc.cta_group::1.sync.aligned.b32 %0, %1;" :: "r"(t), "r"(n))
#define TC_RELINQ()       asm volatile("tcgen05.relinquish_alloc_permit.cta_group::1.sync.aligned;")
#define TC_COMMIT(mb)     asm volatile("tcgen05.commit.cta_group::1.mbarrier::arrive::one.shared::cluster.b64 [%0];" :: "r"(mb) : "memory")
#define TC_FENCE_AFTER()  asm volatile("tcgen05.fence::after_thread_sync;" ::: "memory")
#define TC_FENCE_BEFORE() asm volatile("tcgen05.fence::before_thread_sync;" ::: "memory")
#define TC_WAIT_LD()      asm volatile("tcgen05.wait::ld.sync.aligned;" ::: "memory")
#define FENCE_ASYNC()     asm volatile("fence.proxy.async.shared::cta;" ::: "memory")

__device__ __forceinline__ void mma_tf32_ss(uint32_t d, uint64_t a, uint64_t b,
                                            uint32_t idesc, uint32_t acc) {
    asm volatile(
        "{\n\t.reg .pred p;\n\tsetp.ne.u32 p, %5, 0;\n\t"
        "tcgen05.mma.cta_group::1.kind::tf32 [%0], %1, %2, %3, {%4, %4, %4, %4}, p;\n\t}"
        :: "r"(d), "l"(a), "l"(b), "r"(idesc), "r"(0u), "r"(acc) : "memory");
}

#define TMEM_LD32(r, a) \
    asm volatile("tcgen05.ld.sync.aligned.32x32b.x32.b32 " \
        "{%0,%1,%2,%3,%4,%5,%6,%7,%8,%9,%10,%11,%12,%13,%14,%15," \
        "%16,%17,%18,%19,%20,%21,%22,%23,%24,%25,%26,%27,%28,%29,%30,%31}, [%32];" \
        : "=r"((r)[0]),"=r"((r)[1]),"=r"((r)[2]),"=r"((r)[3]),"=r"((r)[4]),"=r"((r)[5]),"=r"((r)[6]),"=r"((r)[7]), \
          "=r"((r)[8]),"=r"((r)[9]),"=r"((r)[10]),"=r"((r)[11]),"=r"((r)[12]),"=r"((r)[13]),"=r"((r)[14]),"=r"((r)[15]), \
          "=r"((r)[16]),"=r"((r)[17]),"=r"((r)[18]),"=r"((r)[19]),"=r"((r)[20]),"=r"((r)[21]),"=r"((r)[22]),"=r"((r)[23]), \
          "=r"((r)[24]),"=r"((r)[25]),"=r"((r)[26]),"=r"((r)[27]),"=r"((r)[28]),"=r"((r)[29]),"=r"((r)[30]),"=r"((r)[31]) \
        : "r"(a))

static __device__ __forceinline__ uint64_t make_desc(uint32_t addr) {
    const uint64_t base =
        (uint64_t(2) << 61) | (uint64_t(1) << 46) | (uint64_t(64) << 32) | (uint64_t(1) << 16);
    return base | ((uint64_t)(addr >> 4) & 0x3FFF);
}
#define SWZ(o) ((o) ^ (((o) >> 3) & 0x70))
// tf32 idesc: dtype F32 | atype TF32 | btype TF32 | N=256 | M=128
#define IDESC_128x256 (0x10u | (2u<<7) | (2u<<10) | ((256u/8u)<<17) | ((128u/16u)<<24))
#endif // USE_TC

// ---------------- init ----------------
__global__ void init_kernel(float4* out4) {
    int i = blockIdx.x * blockDim.x + threadIdx.x;
    if (i < (NTOK * CDIM) / 4) out4[i] = make_float4(0.f, 0.f, 0.f, 0.f);
    if (i < RPAD) g_tok[i] = -1;
    if (i < NEXP) { g_cnt[i] = 0; g_fill[i] = 0; }
}

// ---------------- weight transpose (+tf32 round) ----------------
__global__ void transpose_kernel(const float* __restrict__ in, float* __restrict__ out,
                                 int R, int Cc) {
    __shared__ float tile[32][33];
    size_t eoff = (size_t)blockIdx.z * R * Cc;
    in += eoff; out += eoff;
    int x = blockIdx.x * 32 + threadIdx.x;
    int y0 = blockIdx.y * 32;
    #pragma unroll
    for (int j = threadIdx.y; j < 32; j += 8)
        tile[j][threadIdx.x] = to_tf32(in[(size_t)(y0 + j) * Cc + x]);
    __syncthreads();
    int ox = y0 + threadIdx.x;
    int oy0 = blockIdx.x * 32;
    #pragma unroll
    for (int j = threadIdx.y; j < 32; j += 8)
        out[(size_t)(oy0 + j) * R + ox] = tile[threadIdx.x][j];
}

// ---------------- router ----------------
__global__ void router_kernel(const float* __restrict__ x, const float* __restrict__ wr) {
    __shared__ float xs[CDIM];
    __shared__ float lg[NEXP];
    int t = blockIdx.x;
    const float4* xrow = (const float4*)(x + (size_t)t * CDIM);
    for (int i = threadIdx.x; i < CDIM / 4; i += blockDim.x)
        ((float4*)xs)[i] = xrow[i];
    __syncthreads();
    int warp = threadIdx.x >> 5, lane = threadIdx.x & 31;
    float s = 0.f;
    #pragma unroll 8
    for (int c = lane; c < CDIM; c += 32) s += xs[c] * wr[c * NEXP + warp];
    #pragma unroll
    for (int o = 16; o > 0; o >>= 1) s += __shfl_xor_sync(0xFFFFFFFFu, s, o);
    if (lane == 0) lg[warp] = s;
    __syncthreads();
    if (threadIdx.x == 0) {
        int i0 = 0; float v0 = lg[0];
        #pragma unroll
        for (int e = 1; e < NEXP; e++) if (lg[e] > v0) { v0 = lg[e]; i0 = e; }
        int i1 = -1; float v1 = -INFINITY;
        #pragma unroll
        for (int e = 0; e < NEXP; e++) if (e != i0 && lg[e] > v1) { v1 = lg[e]; i1 = e; }
        float e1 = __expf(v1 - v0);
        float inv = 1.f / (1.f + e1);
        g_te[t*2+0] = i0; g_tp[t*2+0] = inv;
        g_te[t*2+1] = i1; g_tp[t*2+1] = e1 * inv;
        atomicAdd(&g_cnt[i0], 1);
        atomicAdd(&g_cnt[i1], 1);
    }
}

__global__ void offsets_kernel() {
    if (threadIdx.x == 0) {
        int b = 0;
        for (int e = 0; e < NEXP; e++) { g_base[e] = b; b += ((g_cnt[e] + 127) >> 7) << 7; }
    }
}

__global__ void scatter_kernel() {
    int t = blockIdx.x * blockDim.x + threadIdx.x;
    if (t >= NTOK) return;
    #pragma unroll
    for (int k = 0; k < 2; k++) {
        int e = g_te[t*2+k];
        int pos = g_base[e] + atomicAdd(&g_fill[e], 1);
        g_tok[pos] = t;
        g_w[pos] = g_tp[t*2+k];
    }
}

// ---------------- GEMM1: M=128 N=256 K-chunk=32, fused SwiGLU ----------------
#define G1_A(s)  ((s)*16384)
#define G1_B1(s) (32768 + (s)*32768)
#define G1_B2(s) (98304 + (s)*32768)
#define G1_CTRL  163840
#define G1_SMEM  (163840 + 1088 + 1024)

__global__ __launch_bounds__(256) void gemm1_kernel(const float* __restrict__ x) {
    int e = blockIdx.z;
    int cnt = g_cnt[e];
    int rt = blockIdx.y;
    if (rt * 128 >= cnt) return;
    int r0 = g_base[e] + rt * 128;
    int f0 = blockIdx.x * 256;
    int t = threadIdx.x;
    const float* b1base = g_w1t + ((size_t)e * FDIM + f0) * CDIM;
    const float* b2base = g_w3t + ((size_t)e * FDIM + f0) * CDIM;

#if USE_TC
    extern __shared__ char dynsmem[];
    uint32_t raw = smem_u32(dynsmem);
    uint32_t sbase = (raw + 1023) & ~1023u;
    char* smb = dynsmem + (sbase - raw);
    uint32_t ctrl = sbase + G1_CTRL;
    int*   s_tok = (int*)(smb + G1_CTRL + 64);
    float* s_w   = (float*)(smb + G1_CTRL + 576);

    int wid = t >> 5, lid = t & 31;
    if (wid == 0) { TC_ALLOC(ctrl, 512); TC_RELINQ(); }
    if (t < 128) {
        int tk = g_tok[r0 + t];
        s_tok[t] = tk < 0 ? 0 : tk;
        s_w[t]   = tk < 0 ? 0.f : g_w[r0 + t];
    }
    if (t == 0) { MBAR_INIT(ctrl + 16, 1); MBAR_INIT(ctrl + 24, 1); }
    __syncthreads();
    uint32_t tmem;
    asm volatile("ld.shared.b32 %0, [%1];" : "=r"(tmem) : "r"(ctrl));

    int ph0 = 0, ph1 = 0;
    for (int kc = 0; kc < CDIM / 32; kc++) {
        int s = kc & 1;
        if (kc >= 2) {
            if (s == 0) { mbar_wait(ctrl + 16, ph0); ph0 ^= 1; }
            else        { mbar_wait(ctrl + 24, ph1); ph1 ^= 1; }
        }
        int k0 = kc * 32;
        #pragma unroll
        for (int i = 0; i < 4; i++) {
            int idx = t + i * 256;
            int row = idx >> 3, c4 = idx & 7;
            float4 v = *(const float4*)(x + (size_t)s_tok[row] * CDIM + k0 + c4 * 4);
            v.x = to_tf32(v.x); v.y = to_tf32(v.y); v.z = to_tf32(v.z); v.w = to_tf32(v.w);
            *(float4*)(smb + G1_A(s) + SWZ(row * 128 + c4 * 16)) = v;
        }
        #pragma unroll
        for (int i = 0; i < 8; i++) {
            int idx = t + i * 256;
            int row = idx >> 3, c4 = idx & 7;
            size_t off = (size_t)row * CDIM + k0 + c4 * 4;
            *(float4*)(smb + G1_B1(s) + SWZ(row * 128 + c4 * 16)) = *(const float4*)(b1base + off);
            *(float4*)(smb + G1_B2(s) + SWZ(row * 128 + c4 * 16)) = *(const float4*)(b2base + off);
        }
        __syncthreads();
        if (wid == 0 && elect_one()) {
            FENCE_ASYNC();
            uint64_t ad  = make_desc(sbase + G1_A(s));
            uint64_t b1d = make_desc(sbase + G1_B1(s));
            uint64_t b2d = make_desc(sbase + G1_B2(s));
            #pragma unroll
            for (int j = 0; j < 4; j++) {
                uint32_t acc = (kc > 0 || j > 0) ? 1u : 0u;
                mma_tf32_ss(tmem + 0,   ad + j*2, b1d + j*2, IDESC_128x256, acc);
                mma_tf32_ss(tmem + 256, ad + j*2, b2d + j*2, IDESC_128x256, acc);
            }
            TC_COMMIT(ctrl + 16 + s * 8);
        }
    }
    mbar_wait(ctrl + 16, ph0);
    mbar_wait(ctrl + 24, ph1);
    TC_FENCE_AFTER();

    {   // 8-warp epilogue: warp = (subpartition wid&3) x (column half wid>>2)
        int wq = wid & 3, half = wid >> 2;
        int m = wq * 32 + lid;
        float wgt = s_w[m];
        float* hrow = g_H + (size_t)(r0 + m) * FDIM + f0 + half * 128;
        #pragma unroll
        for (int base = 0; base < 128; base += 32) {
            uint32_t rg[32], ru[32];
            TMEM_LD32(rg, tmem + half * 128 + base);
            TMEM_LD32(ru, tmem + 256 + half * 128 + base);
            TC_WAIT_LD();
            #pragma unroll
            for (int j = 0; j < 32; j += 4) {
                float4 h4;
                float g0 = __uint_as_float(rg[j+0]), u0 = __uint_as_float(ru[j+0]);
                float g1 = __uint_as_float(rg[j+1]), u1 = __uint_as_float(ru[j+1]);
                float g2 = __uint_as_float(rg[j+2]), u2 = __uint_as_float(ru[j+2]);
                float g3 = __uint_as_float(rg[j+3]), u3 = __uint_as_float(ru[j+3]);
                h4.x = to_tf32(g0 / (1.f + __expf(-g0)) * u0 * wgt);
                h4.y = to_tf32(g1 / (1.f + __expf(-g1)) * u1 * wgt);
                h4.z = to_tf32(g2 / (1.f + __expf(-g2)) * u2 * wgt);
                h4.w = to_tf32(g3 / (1.f + __expf(-g3)) * u3 * wgt);
                *(float4*)(hrow + base + j) = h4;
            }
        }
        TC_FENCE_BEFORE();
    }
    __syncthreads();
    if (wid == 0) TC_DEALLOC(tmem, 512);
#else
    // FFMA fallback — only used if the driver ever JITs the compute_103 PTX.
    int row = t & 127, half = t >> 7;
    int tk = g_tok[r0 + row];
    float wgt = tk < 0 ? 0.f : g_w[r0 + row];
    int mytok = tk < 0 ? 0 : tk;
    const float* xr = x + (size_t)mytok * CDIM;
    for (int c = 0; c < 128; c++) {
        int col = half * 128 + c;
        const float* w1r = b1base + (size_t)col * CDIM;
        const float* w3r = b2base + (size_t)col * CDIM;
        float sg = 0.f, su = 0.f;
        for (int k = 0; k < CDIM; k += 4) {
            float4 xv = *(const float4*)(xr + k);
            float4 a = *(const float4*)(w1r + k);
            float4 b = *(const float4*)(w3r + k);
            sg += xv.x*a.x + xv.y*a.y + xv.z*a.z + xv.w*a.w;
            su += xv.x*b.x + xv.y*b.y + xv.z*b.z + xv.w*b.w;
        }
        g_H[(size_t)(r0 + row) * FDIM + f0 + col] = sg / (1.f + __expf(-sg)) * su * wgt;
    }
#endif
}

// ---------------- GEMM2: M=128 N=256, K=1024, atomic combine ----------------
#define G2_A(s)  ((s)*16384)
#define G2_B(s)  (32768 + (s)*32768)
#define G2_CTRL  98304
#define G2_SMEM  (98304 + 1088 + 1024)

__global__ __launch_bounds__(256) void gemm2_kernel(float* __restrict__ out) {
    int e = blockIdx.z;
    int cnt = g_cnt[e];
    int rt = blockIdx.y;
    if (rt * 128 >= cnt) return;
    int r0 = g_base[e] + rt * 128;
    int c0 = blockIdx.x * 256;
    int t = threadIdx.x;
    const float* Bbase = g_w2t + ((size_t)e * CDIM + c0) * FDIM;

#if USE_TC
    extern __shared__ char dynsmem[];
    uint32_t raw = smem_u32(dynsmem);
    uint32_t sbase = (raw + 1023) & ~1023u;
    char* smb = dynsmem + (sbase - raw);
    uint32_t ctrl = sbase + G2_CTRL;
    int* s_tok = (int*)(smb + G2_CTRL + 64);

    int wid = t >> 5, lid = t & 31;
    if (wid == 0) { TC_ALLOC(ctrl, 256); TC_RELINQ(); }
    if (t < 128) s_tok[t] = g_tok[r0 + t];
    if (t == 0) { MBAR_INIT(ctrl + 16, 1); MBAR_INIT(ctrl + 24, 1); }
    __syncthreads();
    uint32_t tmem;
    asm volatile("ld.shared.b32 %0, [%1];" : "=r"(tmem) : "r"(ctrl));

    const float* Abase = g_H + (size_t)r0 * FDIM;
    int ph0 = 0, ph1 = 0;
    for (int kc = 0; kc < FDIM / 32; kc++) {
        int s = kc & 1;
        if (kc >= 2) {
            if (s == 0) { mbar_wait(ctrl + 16, ph0); ph0 ^= 1; }
            else        { mbar_wait(ctrl + 24, ph1); ph1 ^= 1; }
        }
        int k0 = kc * 32;
        #pragma unroll
        for (int i = 0; i < 4; i++) {
            int idx = t + i * 256;
            int row = idx >> 3, c4 = idx & 7;
            *(float4*)(smb + G2_A(s) + SWZ(row * 128 + c4 * 16)) =
                *(const float4*)(Abase + (size_t)row * FDIM + k0 + c4 * 4);
        }
        #pragma unroll
        for (int i = 0; i < 8; i++) {
            int idx = t + i * 256;
            int row = idx >> 3, c4 = idx & 7;
            *(float4*)(smb + G2_B(s) + SWZ(row * 128 + c4 * 16)) =
                *(const float4*)(Bbase + (size_t)row * FDIM + k0 + c4 * 4);
        }
        __syncthreads();
        if (wid == 0 && elect_one()) {
            FENCE_ASYNC();
            uint64_t ad = make_desc(sbase + G2_A(s));
            uint64_t bd = make_desc(sbase + G2_B(s));
            #pragma unroll
            for (int j = 0; j < 4; j++) {
                uint32_t acc = (kc > 0 || j > 0) ? 1u : 0u;
                mma_tf32_ss(tmem, ad + j*2, bd + j*2, IDESC_128x256, acc);
            }
            TC_COMMIT(ctrl + 16 + s * 8);
        }
    }
    mbar_wait(ctrl + 16, ph0);
    mbar_wait(ctrl + 24, ph1);
    TC_FENCE_AFTER();

    {   // 8-warp epilogue; TMEM loads UNCONDITIONAL (warp-collective!),
        // only the atomic stores are predicated on valid token.
        int wq = wid & 3, half = wid >> 2;
        int m = wq * 32 + lid;
        int tok = s_tok[m];
        float* orow = out + (size_t)(tok < 0 ? 0 : tok) * CDIM + c0 + half * 128;
        #pragma unroll
        for (int base = 0; base < 128; base += 32) {
            uint32_t r[32];
            TMEM_LD32(r, tmem + half * 128 + base);
            TC_WAIT_LD();
            if (tok >= 0) {
                #pragma unroll
                for (int j = 0; j < 32; j++)
                    atomicAdd(&orow[base + j], __uint_as_float(r[j]));
            }
        }
        TC_FENCE_BEFORE();
    }
    __syncthreads();
    if (wid == 0) TC_DEALLOC(tmem, 256);
#else
    // FFMA fallback
    int row = t & 127, half = t >> 7;
    int tok = g_tok[r0 + row];
    if (tok < 0) return;
    const float* hr = g_H + (size_t)(r0 + row) * FDIM;
    for (int c = 0; c < 128; c++) {
        int col = half * 128 + c;
        const float* w2r = Bbase + (size_t)col * FDIM;
        float sv = 0.f;
        for (int k = 0; k < FDIM; k += 4) {
            float4 hv = *(const float4*)(hr + k);
            float4 b = *(const float4*)(w2r + k);
            sv += hv.x*b.x + hv.y*b.y + hv.z*b.z + hv.w*b.w;
        }
        atomicAdd(&out[(size_t)tok * CDIM + c0 + col], sv);
    }
#endif
}

// ---------------- launch ----------------
extern "C" void kernel_launch(void* const* d_in, const int* in_sizes, int n_in,
                              void* d_out, int out_size) {
    const float* x  = (const float*)d_in[0];
    const float* wr = (const float*)d_in[1];
    const float* w1 = (const float*)d_in[2];
    const float* w3 = (const float*)d_in[3];
    const float* w2 = (const float*)d_in[4];
    float* out = (float*)d_out;

    cudaFuncSetAttribute(gemm1_kernel, cudaFuncAttributeMaxDynamicSharedMemorySize, G1_SMEM);
    cudaFuncSetAttribute(gemm2_kernel, cudaFuncAttributeMaxDynamicSharedMemorySize, G2_SMEM);

    int init_elems = (NTOK * CDIM) / 4;
    init_kernel<<<(init_elems + 255) / 256, 256>>>((float4*)out);

    float* w1t; cudaGetSymbolAddress((void**)&w1t, g_w1t);
    float* w3t; cudaGetSymbolAddress((void**)&w3t, g_w3t);
    float* w2t; cudaGetSymbolAddress((void**)&w2t, g_w2t);
    dim3 tb(32, 8);
    transpose_kernel<<<dim3(FDIM/32, CDIM/32, NEXP), tb>>>(w1, w1t, CDIM, FDIM);
    transpose_kernel<<<dim3(FDIM/32, CDIM/32, NEXP), tb>>>(w3, w3t, CDIM, FDIM);
    transpose_kernel<<<dim3(CDIM/32, FDIM/32, NEXP), tb>>>(w2, w2t, FDIM, CDIM);

    router_kernel<<<NTOK, 256>>>(x, wr);
    offsets_kernel<<<1, 32>>>();
    scatter_kernel<<<(NTOK + 255) / 256, 256>>>();

    gemm1_kernel<<<dim3(FDIM/256, 64, NEXP), 256, G1_SMEM>>>(x);
    gemm2_kernel<<<dim3(CDIM/256, 64, NEXP), 256, G2_SMEM>>>(out);
}